// round 16
// baseline (speedup 1.0000x reference)
#include <cuda_runtime.h>
#include <cstdint>

#define BATCH 256
#define NNODE 2048
#define EMB   128
#define HEADS 8
#define DK    16
#define SPLITS 8
#define CHUNK (NNODE / SPLITS)   // 256 rows per CTA, 64 per warp (4 warps)

// packed dual-fp32 ops (sm_103a FFMA2 path — only reachable via PTX)
#define FMA2(d, a, b, c) asm("fma.rn.f32x2 %0, %1, %2, %3;" : "=l"(d) : "l"(a), "l"(b), "l"(c))
#define MUL2(d, a, b)    asm("mul.rn.f32x2 %0, %1, %2;"     : "=l"(d) : "l"(a), "l"(b))
#define EX2(d, a)        asm("ex2.approx.f32 %0, %1;" : "=f"(d) : "f"(a))

// ---- scratch (no allocations allowed in kernel_launch) ----
__device__ float g_P[BATCH * HEADS * EMB];                 // P[b,h,:] = scale*log2e * Wk^T q
__device__ float g_qb[BATCH * HEADS];                      // scale*log2e * q_h . bk_h
__device__ float g_partA[SPLITS * BATCH * HEADS * EMB];    // partial weighted-emb sums
__device__ float g_partL[SPLITS * BATCH * HEADS];          // partial softmax denominators
__device__ int   g_flagP[BATCH] = {};                      // 0=unclaimed 1=claimed 2=P ready
__device__ int   g_cnt[BATCH]  = {};                       // arrival counter per batch

// ============================================================================
// ONE fused kernel. Grid (SPLITS, BATCH), 128 threads.
//  - per-CTA mask-format probe (4KB, L2 broadcast)
//  - first arriver per b claims P production (CAS), siblings spin (acquire)
//  - streaming masked softmax + weighted emb accumulation (unchanged core)
//  - 8th arriver per b combines partials + V projection + resets flags
// ============================================================================
__global__ void __launch_bounds__(128) k_fused(
    const float* __restrict__ ctx,  const float* __restrict__ emb,
    const void*  __restrict__ maskp,
    const float* __restrict__ Wq,   const float* __restrict__ bq,
    const float* __restrict__ Wk,   const float* __restrict__ bk,
    const float* __restrict__ Wv,   const float* __restrict__ bv,
    float* __restrict__ out)
{
    const int sIdx = blockIdx.x, b = blockIdx.y;
    const int t = threadIdx.x;
    const int w = t >> 5, lane = t & 31;

    __shared__ float cs[EMB], qs[EMB];
    __shared__ int   sGood, sRole, sLast;
    __shared__ float4 sAcc[4 * 8 * 32];   // 16 KB epilogue scratch
    __shared__ float  sL[4][8];
    __shared__ float  ctxs[HEADS][EMB];   // combine scratch (4 KB)
    __shared__ float  invl[HEADS];

    // ---- per-CTA mask element-width probe: 4-byte bools are words in
    // {0,1,0x3F800000}; byte-packed bools match only ~12.5% of the time.
    if (t == 0) sGood = 0;
    __syncthreads();
    {
        const unsigned* mw = (const unsigned*)maskp;
        int good = 0;
#pragma unroll
        for (int i = 0; i < 8; i++) {
            unsigned wv = mw[t * 8 + i];
            good += (wv == 0u) || (wv == 1u) || (wv == 0x3F800000u);
        }
        atomicAdd(&sGood, good);
    }
    __syncthreads();
    const bool fmt4 = (sGood >= 922);

    // ---- mask load & live-row bitmap (independent of P)
    const int rowBase = sIdx * CHUNK + w * 64;
    const size_t mbase = (size_t)b * NNODE + rowBase;
    bool um0, um1;
    if (fmt4) {
        const unsigned* mi = (const unsigned*)maskp;
        um0 = (mi[mbase + lane]      == 0u);
        um1 = (mi[mbase + 32 + lane] == 0u);
    } else {
        const unsigned char* mu = (const unsigned char*)maskp;
        um0 = (mu[mbase + lane]      == 0);
        um1 = (mu[mbase + 32 + lane] == 0);
    }
    unsigned long long rem =
        (unsigned long long)__ballot_sync(0xffffffffu, um0) |
        ((unsigned long long)__ballot_sync(0xffffffffu, um1) << 32);

    // ---- P production: first arriver per b claims it
    if (t == 0) sRole = atomicCAS(&g_flagP[b], 0, 1);
    __syncthreads();
    const float scale = 0.25f * 1.4426950408889634f;   // (1/sqrt(dk))*log2(e)
    if (sRole == 0) {
        // produce q = ctx@Wq^T+bq (8-lane groups per row, coalesced)
        cs[t] = ctx[b * EMB + t];
        __syncthreads();
        {
            const int g2 = lane >> 3, k8 = lane & 7;
            const float4* cs4 = (const float4*)cs;
#pragma unroll 4
            for (int i = 0; i < 8; i++) {
                const int r = w * 32 + i * 4 + g2;
                const float4* wr = (const float4*)(Wq + r * EMB);
                float part = 0.f;
#pragma unroll
                for (int j = 0; j < 4; j++) {
                    float4 wv = wr[k8 + 8 * j];
                    float4 c  = cs4[k8 + 8 * j];
                    part = fmaf(wv.x, c.x, part); part = fmaf(wv.y, c.y, part);
                    part = fmaf(wv.z, c.z, part); part = fmaf(wv.w, c.w, part);
                }
                part += __shfl_xor_sync(0xffffffffu, part, 4);
                part += __shfl_xor_sync(0xffffffffu, part, 2);
                part += __shfl_xor_sync(0xffffffffu, part, 1);
                if (k8 == 0) qs[r] = part + bq[r];
            }
        }
        __syncthreads();
#pragma unroll
        for (int h = 0; h < HEADS; h++) {
            float p = 0.f;
#pragma unroll
            for (int d = 0; d < DK; d++)
                p = fmaf(qs[h * DK + d], Wk[(h * DK + d) * EMB + t], p);
            g_P[(b * HEADS + h) * EMB + t] = p * scale;
        }
        if (t < HEADS) {
            float s = 0.f;
#pragma unroll
            for (int d = 0; d < DK; d++) s = fmaf(qs[t * DK + d], bk[t * DK + d], s);
            g_qb[b * HEADS + t] = s * scale;
        }
        __threadfence();
        __syncthreads();              // CTA-internal visibility of g_P writes
        if (t == 0)
            asm volatile("st.release.gpu.u32 [%0], %1;" :: "l"(&g_flagP[b]), "r"(2u) : "memory");
    } else {
        if (t == 0) {
            unsigned v;
            do {
                asm volatile("ld.acquire.gpu.u32 %0, [%1];" : "=r"(v) : "l"(&g_flagP[b]) : "memory");
                if (v != 2u) __nanosleep(64);
            } while (v != 2u);
        }
        __syncthreads();
        __threadfence();              // order subsequent g_P reads
    }

    // ---- load per-lane P slices (f32x2-packed) + my head's bias
    unsigned long long p01[8], p23[8];
    {
        const ulonglong2* Pv = (const ulonglong2*)g_P + (size_t)b * (HEADS * EMB / 4);
#pragma unroll
        for (int h = 0; h < 8; h++) {
            ulonglong2 t2 = Pv[h * 32 + lane];
            p01[h] = t2.x; p23[h] = t2.y;
        }
    }
    const float qb_mine = g_qb[b * HEADS + (lane >> 2)];

    // ---- streaming loop (batches of 4 live rows)
    unsigned long long acc01[8], acc23[8];
#pragma unroll
    for (int h = 0; h < 8; h++) { acc01[h] = 0ull; acc23[h] = 0ull; }
    float lacc = 0.f;

    const ulonglong2* e4 = (const ulonglong2*)emb + ((size_t)b * NNODE + rowBase) * (EMB / 4) + lane;

    int c[4], n[4];
    ulonglong2 E[4], N[4];
#pragma unroll
    for (int j = 0; j < 4; j++) {
        c[j] = rem ? (__ffsll((long long)rem) - 1) : 64;
        if (c[j] < 64) rem &= rem - 1;
    }
#pragma unroll
    for (int j = 0; j < 4; j++) {
        E[j].x = 0ull; E[j].y = 0ull;
        if (c[j] < 64) E[j] = e4[(size_t)c[j] * (EMB / 4)];
    }

    while (c[0] < 64) {
#pragma unroll
        for (int j = 0; j < 4; j++) {
            n[j] = rem ? (__ffsll((long long)rem) - 1) : 64;
            if (n[j] < 64) rem &= rem - 1;
        }
#pragma unroll
        for (int j = 0; j < 4; j++) {
            N[j].x = 0ull; N[j].y = 0ull;
            if (n[j] < 64) N[j] = e4[(size_t)n[j] * (EMB / 4)];
        }

        float vm[32];
#pragma unroll
        for (int h = 0; h < 8; h++)
#pragma unroll
            for (int r = 0; r < 4; r++) {
                unsigned long long s2;
                MUL2(s2, p01[h], E[r].x);
                FMA2(s2, p23[h], E[r].y, s2);
                unsigned lo, hi;
                asm("mov.b64 {%0, %1}, %2;" : "=r"(lo), "=r"(hi) : "l"(s2));
                vm[h * 4 + r] = __uint_as_float(lo) + __uint_as_float(hi);
            }

        // 5-stage 32-value transpose-reduce: lane l ends with full sum vm[l]
#pragma unroll
        for (int V = 16; V >= 1; V >>= 1) {
            const bool up = (lane & V) != 0;
#pragma unroll
            for (int j = 0; j < V; j++) {
                float lo = vm[j], hi = vm[j + V];
                float mine  = up ? hi : lo;
                float other = up ? lo : hi;
                vm[j] = mine + __shfl_xor_sync(0xffffffffu, other, V);
            }
        }

        int cr = (lane & 1) ? ((lane & 2) ? c[3] : c[1])
                            : ((lane & 2) ? c[2] : c[0]);
        float wlane;
        EX2(wlane, vm[0] + qb_mine);
        wlane = (cr < 64) ? wlane : 0.f;
        lacc += wlane;

#pragma unroll
        for (int h = 0; h < 8; h++) {
#pragma unroll
            for (int r = 0; r < 4; r++) {
                float wgt = __shfl_sync(0xffffffffu, wlane, h * 4 + r);
                unsigned long long wh2;
                unsigned whu = __float_as_uint(wgt);
                asm("mov.b64 %0, {%1, %1};" : "=l"(wh2) : "r"(whu));
                FMA2(acc01[h], wh2, E[r].x, acc01[h]);
                FMA2(acc23[h], wh2, E[r].y, acc23[h]);
            }
        }
#pragma unroll
        for (int j = 0; j < 4; j++) { c[j] = n[j]; E[j] = N[j]; }
    }

    lacc += __shfl_xor_sync(0xffffffffu, lacc, 1);
    lacc += __shfl_xor_sync(0xffffffffu, lacc, 2);

    // ---- cross-warp reduce + partial write
#pragma unroll
    for (int h = 0; h < 8; h++) {
        unsigned a0, a1, a2, a3;
        asm("mov.b64 {%0, %1}, %2;" : "=r"(a0), "=r"(a1) : "l"(acc01[h]));
        asm("mov.b64 {%0, %1}, %2;" : "=r"(a2), "=r"(a3) : "l"(acc23[h]));
        sAcc[(w * 8 + h) * 32 + lane] = make_float4(__uint_as_float(a0), __uint_as_float(a1),
                                                    __uint_as_float(a2), __uint_as_float(a3));
    }
    if ((lane & 3) == 0) sL[w][lane >> 2] = lacc;
    __syncthreads();

    {
        float4* outA = (float4*)g_partA + ((size_t)sIdx * BATCH + b) * 256;
#pragma unroll
        for (int r = 0; r < 2; r++) {
            int idx = r * 128 + t;
            float4 a = sAcc[idx];
#pragma unroll
            for (int ww = 1; ww < 4; ww++) {
                float4 o = sAcc[ww * 256 + idx];
                a.x += o.x; a.y += o.y; a.z += o.z; a.w += o.w;
            }
            outA[idx] = a;
        }
        if (t < 8) {
            float l = 0.f;
#pragma unroll
            for (int ww = 0; ww < 4; ww++) l += sL[ww][t];
            g_partL[(sIdx * BATCH + b) * HEADS + t] = l;
        }
    }

    // ---- arrival count; 8th arriver combines + resets
    __threadfence();
    __syncthreads();
    if (t == 0) sLast = atomicAdd(&g_cnt[b], 1);
    __syncthreads();
    if (sLast != SPLITS - 1) return;
    __threadfence();   // acquire: other CTAs' partials

    if (t < 8) {
        float l = 0.f;
#pragma unroll
        for (int s = 0; s < SPLITS; s++) l += g_partL[(s * BATCH + b) * HEADS + t];
        invl[t] = 1.f / l;
    }
#pragma unroll
    for (int r2 = 0; r2 < 2; r2++) {
        int id = r2 * 128 + t;
        int h = id >> 5, q = id & 31;
        float4 a = make_float4(0.f, 0.f, 0.f, 0.f);
#pragma unroll
        for (int s = 0; s < SPLITS; s++) {
            float4 o = ((const float4*)g_partA)[((size_t)(s * BATCH + b) * HEADS + h) * 32 + q];
            a.x += o.x; a.y += o.y; a.z += o.z; a.w += o.w;
        }
        ((float4*)ctxs[h])[q] = a;
    }
    __syncthreads();

    {
        const int g2 = lane >> 3, k8 = lane & 7;
#pragma unroll
        for (int i = 0; i < 8; i++) {
            const int r = w * 32 + i * 4 + g2;          // 0..127
            const int h = r >> 4;
            const float4* wr = (const float4*)(Wv + r * EMB);
            const float4* c4 = (const float4*)ctxs[h];
            float part = 0.f;
#pragma unroll
            for (int j = 0; j < 4; j++) {
                float4 wv = wr[k8 + 8 * j];
                float4 c  = c4[k8 + 8 * j];
                part = fmaf(wv.x, c.x, part); part = fmaf(wv.y, c.y, part);
                part = fmaf(wv.z, c.z, part); part = fmaf(wv.w, c.w, part);
            }
            part += __shfl_xor_sync(0xffffffffu, part, 4);
            part += __shfl_xor_sync(0xffffffffu, part, 2);
            part += __shfl_xor_sync(0xffffffffu, part, 1);
            if (k8 == 0) out[b * EMB + r] = fmaf(part, invl[h], bv[r]);
        }
    }
    __syncthreads();
    if (t == 0) { g_cnt[b] = 0; g_flagP[b] = 0; }   // reset for next graph replay
}

// ============================================================================
extern "C" void kernel_launch(void* const* d_in, const int* in_sizes, int n_in,
                              void* d_out, int out_size)
{
    const float* ctx = (const float*)d_in[0];
    const float* emb = (const float*)d_in[1];
    const void*  msk = d_in[2];
    const float* Wq  = (const float*)d_in[3];
    const float* bq  = (const float*)d_in[4];
    const float* Wk  = (const float*)d_in[5];
    const float* bk  = (const float*)d_in[6];
    const float* Wv  = (const float*)d_in[7];
    const float* bv  = (const float*)d_in[8];
    float* out = (float*)d_out;

    k_fused<<<dim3(SPLITS, BATCH), 128>>>(ctx, emb, msk, Wq, bq, Wk, bk, Wv, bv, out);
}